// round 2
// baseline (speedup 1.0000x reference)
#include <cuda_runtime.h>

// out[i*2+0] = sum of edge_attr[e] for edges with edgeij_pair[0][e] == i
// out[i*2+1] = vertex_attr[i*2+1]

__global__ void init_out_kernel(const float4* __restrict__ vattr,
                                float4* __restrict__ out, int n_pairs) {
    // Each float4 covers 2 vertex rows: {x0,y0,x1,y1} -> {0,y0,0,y1}
    int i = blockIdx.x * blockDim.x + threadIdx.x;
    if (i < n_pairs) {
        float4 v = vattr[i];
        float4 o;
        o.x = 0.0f; o.y = v.y;
        o.z = 0.0f; o.w = v.w;
        out[i] = o;
    }
}

__global__ void init_out_tail_kernel(const float* __restrict__ vattr,
                                     float* __restrict__ out,
                                     int start, int n_vertices) {
    int i = start + blockIdx.x * blockDim.x + threadIdx.x;
    if (i < n_vertices) {
        out[2 * i + 0] = 0.0f;
        out[2 * i + 1] = vattr[2 * i + 1];
    }
}

// 8 edges per thread: two int4 index loads + two float4 value loads issued
// up-front (max MLP), then 8 REDs. Hot path is branch-free (grid sized so
// only the last thread can hit the tail).
__global__ void scatter_add_kernel(const int4* __restrict__ idx4,
                                   const float4* __restrict__ val4,
                                   float* __restrict__ out, int n_edges) {
    int t = blockIdx.x * blockDim.x + threadIdx.x;
    int g = t * 2;                 // group of two float4/int4 quads
    int base = g * 4;
    if (base + 7 < n_edges) {
        int4   ia = idx4[g];
        int4   ib = idx4[g + 1];
        float4 va = val4[g];
        float4 vb = val4[g + 1];
        atomicAdd(out + 2 * ia.x, va.x);
        atomicAdd(out + 2 * ia.y, va.y);
        atomicAdd(out + 2 * ia.z, va.z);
        atomicAdd(out + 2 * ia.w, va.w);
        atomicAdd(out + 2 * ib.x, vb.x);
        atomicAdd(out + 2 * ib.y, vb.y);
        atomicAdd(out + 2 * ib.z, vb.z);
        atomicAdd(out + 2 * ib.w, vb.w);
    } else if (base < n_edges) {
        const int* idx = (const int*)idx4;
        const float* val = (const float*)val4;
        for (int e = base; e < n_edges; ++e)
            atomicAdd(out + 2 * idx[e], val[e]);
    }
}

extern "C" void kernel_launch(void* const* d_in, const int* in_sizes, int n_in,
                              void* d_out, int out_size) {
    // metadata order: vertex_attr [N,2] f32, edgeij_pair [2,E] i32,
    //                 edge_attr [E,1] f32, g [1,1] f32, batch [N] i32
    const float* vattr = (const float*)d_in[0];
    const int*   eij   = (const int*)d_in[1];
    const float* eattr = (const float*)d_in[2];
    float* out = (float*)d_out;

    int n_vertices = in_sizes[0] / 2;
    int n_edges    = in_sizes[2];
    const int* src_idx = eij; // row 0 of [2, E]

    {
        int n_pairs = n_vertices / 2;  // float4 = 2 rows
        int threads = 256;
        int blocks = (n_pairs + threads - 1) / threads;
        if (blocks > 0)
            init_out_kernel<<<blocks, threads>>>(
                (const float4*)vattr, (float4*)out, n_pairs);
        if (n_vertices & 1) {
            init_out_tail_kernel<<<1, 32>>>(vattr, out, n_pairs * 2, n_vertices);
        }
    }
    {
        int threads = 256;
        int per_block = threads * 8;
        int blocks = (n_edges + per_block - 1) / per_block;
        scatter_add_kernel<<<blocks, threads>>>(
            (const int4*)src_idx, (const float4*)eattr, out, n_edges);
    }
}